// round 16
// baseline (speedup 1.0000x reference)
#include <cuda_runtime.h>
#include <cuda_bf16.h>

// Problem constants
#define B_   4
#define CIN  64
#define C_   256
#define N_   1729          // 1 cls + 12*12*12 tokens
#define P_   1728
#define NH   8
#define HD   32
#define DEPTH 2
#define M_TOK (B_ * N_)    // 6916

typedef unsigned int uint32;

// ---- bf16 helpers ----
__device__ __forceinline__ uint32 bf2(float lo, float hi) {
    __nv_bfloat162 t = __floats2bfloat162_rn(lo, hi);   // lo -> low 16 bits
    return *(uint32*)&t;
}

__device__ __forceinline__ float ex2f(float x) {
    float r; asm("ex2.approx.f32 %0, %1;" : "=f"(r) : "f"(x)); return r;
}

// bf16 m16n8k16 mma: D = A @ B^T + D  (A,B bf16, C/D fp32)
__device__ __forceinline__ void mma16816(float* c, const uint32* a, uint32 b0, uint32 b1) {
    asm volatile(
        "mma.sync.aligned.m16n8k16.row.col.f32.bf16.bf16.f32 "
        "{%0,%1,%2,%3}, {%4,%5,%6,%7}, {%8,%9}, {%0,%1,%2,%3};\n"
        : "+f"(c[0]), "+f"(c[1]), "+f"(c[2]), "+f"(c[3])
        : "r"(a[0]), "r"(a[1]), "r"(a[2]), "r"(a[3]), "r"(b0), "r"(b1));
}

// tf32 m16n8k8 mma
__device__ __forceinline__ void mma_tf32(float* c, const uint32* a, uint32 b0, uint32 b1) {
    asm volatile(
        "mma.sync.aligned.m16n8k8.row.col.f32.tf32.tf32.f32 "
        "{%0,%1,%2,%3}, {%4,%5,%6,%7}, {%8,%9}, {%0,%1,%2,%3};\n"
        : "+f"(c[0]), "+f"(c[1]), "+f"(c[2]), "+f"(c[3])
        : "r"(a[0]), "r"(a[1]), "r"(a[2]), "r"(a[3]), "r"(b0), "r"(b1));
}

__device__ __forceinline__ float cvt_tf32f(float f) {
    uint32 r; asm("cvt.rna.tf32.f32 %0, %1;" : "=r"(r) : "f"(f));
    return __uint_as_float(r);
}

__device__ __forceinline__ void ldsm4(uint32& r0, uint32& r1, uint32& r2, uint32& r3,
                                      uint32 addr) {
    asm volatile("ldmatrix.sync.aligned.m8n8.x4.shared.b16 {%0,%1,%2,%3}, [%4];"
                 : "=r"(r0), "=r"(r1), "=r"(r2), "=r"(r3) : "r"(addr));
}
__device__ __forceinline__ void ldsm4t(uint32& r0, uint32& r1, uint32& r2, uint32& r3,
                                       uint32 addr) {
    asm volatile("ldmatrix.sync.aligned.m8n8.x4.trans.shared.b16 {%0,%1,%2,%3}, [%4];"
                 : "=r"(r0), "=r"(r1), "=r"(r2), "=r"(r3) : "r"(addr));
}

// Scratch (device globals; no cudaMalloc allowed)
__device__ float g_t  [M_TOK * C_];
__device__ float g_y  [M_TOK * C_];
__device__ float g_h  [M_TOK * C_];
__device__ float g_o  [M_TOK * C_];
// bf16 Q/K/V head-major [b, h, n, 32]; Q pre-scaled by log2(e)/sqrt(hd)
__device__ __nv_bfloat16 g_qb[B_ * NH * N_ * HD];
__device__ __nv_bfloat16 g_kb[B_ * NH * N_ * HD];
__device__ __nv_bfloat16 g_vb[B_ * NH * N_ * HD];

// ---------------------------------------------------------------------------
// Patch embed: 8 tokens per block, W_pe values reused x8.
// ---------------------------------------------------------------------------
__global__ __launch_bounds__(256) void embed_kernel(const float* __restrict__ x,
                                                    const float* __restrict__ W_pe,
                                                    const float* __restrict__ b_pe,
                                                    const float* __restrict__ cls) {
    int p0 = blockIdx.x * 8;
    int b  = blockIdx.y;
    int d  = threadIdx.x;

    __shared__ float sx[CIN][8];
#pragma unroll
    for (int i = 0; i < 2; i++) {
        int idx = d + i * 256;
        int c = idx >> 3, tok = idx & 7;
        sx[c][tok] = x[(size_t)(b * CIN + c) * P_ + p0 + tok];
    }
    __syncthreads();

    float acc[8];
    float bp = b_pe[d];
#pragma unroll
    for (int t = 0; t < 8; t++) acc[t] = bp;
#pragma unroll
    for (int c = 0; c < CIN; c++) {
        float w = W_pe[c * C_ + d];
        float4 x0 = *(const float4*)&sx[c][0];
        float4 x1 = *(const float4*)&sx[c][4];
        acc[0] += x0.x * w; acc[1] += x0.y * w;
        acc[2] += x0.z * w; acc[3] += x0.w * w;
        acc[4] += x1.x * w; acc[5] += x1.y * w;
        acc[6] += x1.z * w; acc[7] += x1.w * w;
    }
#pragma unroll
    for (int t = 0; t < 8; t++)
        g_t[(size_t)(b * N_ + 1 + p0 + t) * C_ + d] = acc[t];

    if (blockIdx.x == 0) g_t[(size_t)(b * N_) * C_ + d] = cls[d];
}

// ---------------------------------------------------------------------------
// LayerNorm: warp-per-row, float4 loads, shuffle-only reduction. 8 rows/block.
// ---------------------------------------------------------------------------
__global__ __launch_bounds__(256) void ln_kernel(const float* __restrict__ in,
                                                 float* __restrict__ out,
                                                 const float* __restrict__ g,
                                                 const float* __restrict__ bb) {
    int row = blockIdx.x * 8 + (threadIdx.x >> 5);
    int lane = threadIdx.x & 31;
    if (row >= M_TOK) return;
    const float4* rp = (const float4*)(in + (size_t)row * C_);
    float4 v0 = rp[lane], v1 = rp[lane + 32];
    float s  = (v0.x + v0.y) + (v0.z + v0.w) + (v1.x + v1.y) + (v1.z + v1.w);
    float sq = (v0.x * v0.x + v0.y * v0.y) + (v0.z * v0.z + v0.w * v0.w)
             + (v1.x * v1.x + v1.y * v1.y) + (v1.z * v1.z + v1.w * v1.w);
#pragma unroll
    for (int o = 16; o > 0; o >>= 1) {
        s  += __shfl_xor_sync(0xffffffffu, s,  o);
        sq += __shfl_xor_sync(0xffffffffu, sq, o);
    }
    float mean = s * (1.f / C_);
    float var  = sq * (1.f / C_) - mean * mean;
    float inv  = rsqrtf(var + 1e-5f);

    const float4* gp = (const float4*)g;
    const float4* bp = (const float4*)bb;
    float4* op = (float4*)(out + (size_t)row * C_);
#pragma unroll
    for (int k = 0; k < 2; k++) {
        float4 v = k ? v1 : v0;
        float4 gg = gp[lane + k * 32];
        float4 bbv = bp[lane + k * 32];
        float4 r;
        r.x = (v.x - mean) * inv * gg.x + bbv.x;
        r.y = (v.y - mean) * inv * gg.y + bbv.y;
        r.z = (v.z - mean) * inv * gg.z + bbv.z;
        r.w = (v.w - mean) * inv * gg.w + bbv.w;
        op[lane + k * 32] = r;
    }
}

// ---------------------------------------------------------------------------
// Final LN + transposed scatter, coalesced: 32-token chunk per block.
// ---------------------------------------------------------------------------
__global__ __launch_bounds__(256) void final_ln_kernel(const float* __restrict__ in,
                                                       const float* __restrict__ g,
                                                       const float* __restrict__ bb,
                                                       float* __restrict__ out) {
    __shared__ float tile[32 * 257];
    int b  = blockIdx.y;
    int n0 = blockIdx.x * 32;
    int tid = threadIdx.x;
    int warp = tid >> 5, lane = tid & 31;

#pragma unroll
    for (int i = 0; i < 4; i++) {
        int j = warp + i * 8;            // local row 0..31
        int n = n0 + j;
        if (n >= N_) break;
        const float* rp = in + (size_t)(b * N_ + n) * C_;
        float v[8];
        float s = 0.f, sq = 0.f;
#pragma unroll
        for (int k = 0; k < 8; k++) {
            v[k] = rp[lane + k * 32];
            s += v[k]; sq += v[k] * v[k];
        }
#pragma unroll
        for (int o = 16; o > 0; o >>= 1) {
            s  += __shfl_xor_sync(0xffffffffu, s,  o);
            sq += __shfl_xor_sync(0xffffffffu, sq, o);
        }
        float mean = s * (1.f / C_);
        float var  = sq * (1.f / C_) - mean * mean;
        float inv  = rsqrtf(var + 1e-5f);
#pragma unroll
        for (int k = 0; k < 8; k++) {
            int c = lane + k * 32;
            tile[j * 257 + c] = (v[k] - mean) * inv * g[c] + bb[c];
        }
    }
    __syncthreads();

    int n = n0 + lane;
    if (n >= N_) return;
#pragma unroll
    for (int i = 0; i < 32; i++) {
        int c = warp + i * 8;
        float val = tile[lane * 257 + c];
        if (n == 0) out[b * C_ + c] = val;
        else        out[B_ * C_ + (size_t)(b * C_ + c) * P_ + (n - 1)] = val;
    }
}

// ---------------------------------------------------------------------------
// tf32 tensor-core GEMM, BK=32, register prefetch, ldmatrix fragment loads.
// BM=64, BN=16*NT. 128 threads = 4 warps (2m x 2n).
// A smem [m][k] (stride 36); B smem TRANSPOSED [n][k] (stride 36) so both
// A and B fragments come from ldmatrix.x4 (12 ldmatrix vs 48 LDS.32 per
// warp per k-iter). EPI_QKV writes bf16 head-major q/k/v (q pre-scaled).
// ---------------------------------------------------------------------------
template<int NT, bool EPI_QKV, bool GELU, bool RES>
__global__ __launch_bounds__(128) void gemm_tf32(const float* __restrict__ A,
                                                 const float* __restrict__ W,
                                                 const float* __restrict__ bias,
                                                 float* __restrict__ out,
                                                 int M, int K, int N,
                                                 __nv_bfloat16* __restrict__ qb,
                                                 __nv_bfloat16* __restrict__ kb,
                                                 __nv_bfloat16* __restrict__ vb) {
    constexpr int BN  = 16 * NT;
    constexpr int NB4 = BN / 16;            // B float4 loads per thread (BK=32)
    __shared__ float sA [64][36];           // [m][k]
    __shared__ float sBt[BN][36];           // [n][k] (transposed)
    int tid  = threadIdx.x;
    int warp = tid >> 5, lane = tid & 31;
    int g = lane >> 2, qd = lane & 3;
    int wm = warp >> 1, wn = warp & 1;
    int m0 = blockIdx.y * 64;
    int n0 = blockIdx.x * BN;

    // ldmatrix row-address lanes: matrix = lane>>3, row-in-matrix = lane&7
    int lmat = lane >> 3, lrow = lane & 7;
    uint32 sa_base  = (uint32)__cvta_generic_to_shared(&sA[0][0]);
    uint32 sbt_base = (uint32)__cvta_generic_to_shared(&sBt[0][0]);
    // A frag matrices per (mt): rows wm*32+mt*16+(lmat&1)*8+lrow, col (lmat>>1)*4
    uint32 addrA[2];
#pragma unroll
    for (int mt = 0; mt < 2; mt++)
        addrA[mt] = sa_base +
            (uint32)(((wm * 32 + mt * 16 + (lmat & 1) * 8 + lrow) * 36 + (lmat >> 1) * 4) * 4);
    // B frag matrices per (nt): rows wn*(8NT)+nt*8+lrow, col lmat*4 (two ks per x4)
    uint32 addrB[NT];
#pragma unroll
    for (int nt = 0; nt < NT; nt++)
        addrB[nt] = sbt_base +
            (uint32)(((wn * (8 * NT) + nt * 8 + lrow) * 36 + lmat * 4) * 4);

    float c[2][NT][4];
#pragma unroll
    for (int mt = 0; mt < 2; mt++)
#pragma unroll
        for (int nt = 0; nt < NT; nt++)
#pragma unroll
            for (int j = 0; j < 4; j++) c[mt][nt][j] = 0.f;

    // initial fill (k0 = 0)
#pragma unroll
    for (int i = 0; i < 4; i++) {
        int idx = tid + i * 128;
        int m = idx >> 3, q = idx & 7;
        int gm = m0 + m;
        float4 av = (gm < M) ? *(const float4*)(A + (size_t)gm * K + q * 4)
                             : make_float4(0.f, 0.f, 0.f, 0.f);
        av.x = cvt_tf32f(av.x); av.y = cvt_tf32f(av.y);
        av.z = cvt_tf32f(av.z); av.w = cvt_tf32f(av.w);
        *(float4*)&sA[m][q * 4] = av;
    }
#pragma unroll
    for (int i = 0; i < NB4; i++) {
        int idx = tid + i * 128;
        int kl = idx / (BN / 4), nl = (idx % (BN / 4)) * 4;
        float4 bv4 = *(const float4*)(W + (size_t)kl * N + n0 + nl);
        sBt[nl + 0][kl] = cvt_tf32f(bv4.x);
        sBt[nl + 1][kl] = cvt_tf32f(bv4.y);
        sBt[nl + 2][kl] = cvt_tf32f(bv4.z);
        sBt[nl + 3][kl] = cvt_tf32f(bv4.w);
    }
    __syncthreads();

    for (int k0 = 0; k0 < K; k0 += 32) {
        bool nxt = (k0 + 32) < K;
        float4 apre[4], bpre[NB4];
        if (nxt) {
#pragma unroll
            for (int i = 0; i < 4; i++) {
                int idx = tid + i * 128;
                int m = idx >> 3, q = idx & 7;
                int gm = m0 + m;
                apre[i] = (gm < M) ? *(const float4*)(A + (size_t)gm * K + k0 + 32 + q * 4)
                                   : make_float4(0.f, 0.f, 0.f, 0.f);
            }
#pragma unroll
            for (int i = 0; i < NB4; i++) {
                int idx = tid + i * 128;
                int kl = idx / (BN / 4), nl = (idx % (BN / 4)) * 4;
                bpre[i] = *(const float4*)(W + (size_t)(k0 + 32 + kl) * N + n0 + nl);
            }
        }

        // mma over current tile: 2 ks-pairs, ldmatrix fragments
#pragma unroll
        for (int p = 0; p < 2; p++) {
            uint32 a[2][2][4];     // [ks within pair][mt][reg]
#pragma unroll
            for (int mt = 0; mt < 2; mt++) {
                ldsm4(a[0][mt][0], a[0][mt][1], a[0][mt][2], a[0][mt][3],
                      addrA[mt] + p * 64);
                ldsm4(a[1][mt][0], a[1][mt][1], a[1][mt][2], a[1][mt][3],
                      addrA[mt] + p * 64 + 32);
            }
#pragma unroll
            for (int nt = 0; nt < NT; nt++) {
                uint32 b0, b1, b2, b3;
                ldsm4(b0, b1, b2, b3, addrB[nt] + p * 64);
#pragma unroll
                for (int mt = 0; mt < 2; mt++) {
                    mma_tf32(c[mt][nt], a[0][mt], b0, b1);
                    mma_tf32(c[mt][nt], a[1][mt], b2, b3);
                }
            }
        }
        __syncthreads();

        if (nxt) {
#pragma unroll
            for (int i = 0; i < 4; i++) {
                int idx = tid + i * 128;
                float4 av = apre[i];
                av.x = cvt_tf32f(av.x); av.y = cvt_tf32f(av.y);
                av.z = cvt_tf32f(av.z); av.w = cvt_tf32f(av.w);
                *(float4*)&sA[idx >> 3][(idx & 7) * 4] = av;
            }
#pragma unroll
            for (int i = 0; i < NB4; i++) {
                int idx = tid + i * 128;
                int kl = idx / (BN / 4), nl = (idx % (BN / 4)) * 4;
                float4 bv4 = bpre[i];
                sBt[nl + 0][kl] = cvt_tf32f(bv4.x);
                sBt[nl + 1][kl] = cvt_tf32f(bv4.y);
                sBt[nl + 2][kl] = cvt_tf32f(bv4.z);
                sBt[nl + 3][kl] = cvt_tf32f(bv4.w);
            }
            __syncthreads();
        }
    }

    // q scale includes log2(e) so softmax uses raw ex2
    const float qscale = 0.17677669529663687f * 1.4426950408889634f;

#pragma unroll
    for (int nt = 0; nt < NT; nt++) {
        int col = n0 + wn * (8 * NT) + nt * 8 + 2 * qd;
        float bv0 = (!EPI_QKV && bias) ? bias[col]     : 0.f;
        float bv1 = (!EPI_QKV && bias) ? bias[col + 1] : 0.f;
#pragma unroll
        for (int mt = 0; mt < 2; mt++) {
            int row0 = m0 + wm * 32 + mt * 16 + g;
#pragma unroll
            for (int half = 0; half < 2; half++) {
                int row = row0 + half * 8;
                if (row >= M) continue;
                float v0 = c[mt][nt][half * 2];
                float v1 = c[mt][nt][half * 2 + 1];
                if (EPI_QKV) {
                    int seg = col >> 8;
                    int h   = (col & 255) >> 5;
                    int d   = col & 31;
                    int b   = row / N_, n = row % N_;
                    float sc = (seg == 0) ? qscale : 1.f;
                    __nv_bfloat16* dst = (seg == 0) ? qb : (seg == 1) ? kb : vb;
                    *(uint32*)&dst[((size_t)(b * NH + h) * N_ + n) * HD + d] =
                        bf2(v0 * sc, v1 * sc);
                } else {
                    v0 += bv0; v1 += bv1;
                    if (GELU) { v0 = v0 * normcdff(v0); v1 = v1 * normcdff(v1); }
                    float* op = out + (size_t)row * N + col;
                    if (RES) {
                        float2 prev = *(const float2*)op;
                        *(float2*)op = make_float2(prev.x + v0, prev.y + v1);
                    } else {
                        *(float2*)op = make_float2(v0, v1);
                    }
                }
            }
        }
    }
}

// ---------------------------------------------------------------------------
// Attention tile compute: GUARD=false for fully-valid tiles (no predicates).
// ---------------------------------------------------------------------------
template<bool GUARD>
__device__ __forceinline__ void attn_tile(int kb, int qd, uint32 kaddr, uint32 vaddr,
                                          const uint32 qa[2][2][4],
                                          float oacc[2][4][4], float lsum[2][2]) {
    uint32 pa[2][4][4];
#pragma unroll
    for (int ns = 0; ns < 8; ns++) {
        uint32 b0, b1, b2, b3;
        ldsm4(b0, b1, b2, b3, kaddr + ns * 640);
        float s0[4] = {0.f, 0.f, 0.f, 0.f};
        float s1[4] = {0.f, 0.f, 0.f, 0.f};
        mma16816(s0, qa[0][0], b0, b1);
        mma16816(s0, qa[0][1], b2, b3);
        mma16816(s1, qa[1][0], b0, b1);
        mma16816(s1, qa[1][1], b2, b3);

        float p00, p01, p02, p03, p10, p11, p12, p13;
        if (GUARD) {
            int cb = kb + ns * 8 + 2 * qd;
            bool v0 = cb < N_, v1 = (cb + 1) < N_;
            p00 = v0 ? ex2f(s0[0]) : 0.f;
            p01 = v1 ? ex2f(s0[1]) : 0.f;
            p02 = v0 ? ex2f(s0[2]) : 0.f;
            p03 = v1 ? ex2f(s0[3]) : 0.f;
            p10 = v0 ? ex2f(s1[0]) : 0.f;
            p11 = v1 ? ex2f(s1[1]) : 0.f;
            p12 = v0 ? ex2f(s1[2]) : 0.f;
            p13 = v1 ? ex2f(s1[3]) : 0.f;
        } else {
            p00 = ex2f(s0[0]); p01 = ex2f(s0[1]);
            p02 = ex2f(s0[2]); p03 = ex2f(s0[3]);
            p10 = ex2f(s1[0]); p11 = ex2f(s1[1]);
            p12 = ex2f(s1[2]); p13 = ex2f(s1[3]);
        }
        lsum[0][0] += p00 + p01; lsum[0][1] += p02 + p03;
        lsum[1][0] += p10 + p11; lsum[1][1] += p12 + p13;

        int kk = ns >> 1;
        if (ns & 1) {
            pa[0][kk][2] = bf2(p00, p01); pa[0][kk][3] = bf2(p02, p03);
            pa[1][kk][2] = bf2(p10, p11); pa[1][kk][3] = bf2(p12, p13);
        } else {
            pa[0][kk][0] = bf2(p00, p01); pa[0][kk][1] = bf2(p02, p03);
            pa[1][kk][0] = bf2(p10, p11); pa[1][kk][1] = bf2(p12, p13);
        }
    }

#pragma unroll
    for (int nd = 0; nd < 4; nd++) {
        uint32 b0, b1, b2, b3;
        ldsm4t(b0, b1, b2, b3, vaddr + nd * 16);
        mma16816(oacc[0][nd], pa[0][0], b0, b1);
        mma16816(oacc[0][nd], pa[0][1], b2, b3);
        mma16816(oacc[1][nd], pa[1][0], b0, b1);
        mma16816(oacc[1][nd], pa[1][1], b2, b3);
        ldsm4t(b0, b1, b2, b3, vaddr + nd * 16 + 2560);
        mma16816(oacc[0][nd], pa[0][2], b0, b1);
        mma16816(oacc[0][nd], pa[0][3], b2, b3);
        mma16816(oacc[1][nd], pa[1][2], b0, b1);
        mma16816(oacc[1][nd], pa[1][3], b2, b3);
    }
}

// ---------------------------------------------------------------------------
// bf16 tensor-core flash attention. Single smem buffer, guard hoisted to the
// last tile only. 128 q/CTA, 32 q/warp. Grid 14 x 32 = 448 CTAs.
// ---------------------------------------------------------------------------
__global__ __launch_bounds__(128) void attn_kernel(const __nv_bfloat16* __restrict__ qbuf,
                                                   const __nv_bfloat16* __restrict__ kbuf,
                                                   const __nv_bfloat16* __restrict__ vbuf,
                                                   float* __restrict__ o_out) {
    int qt  = blockIdx.x;
    int bh  = blockIdx.y;
    int b   = bh >> 3;
    int h   = bh & 7;
    int tid = threadIdx.x;
    int warp = tid >> 5, lane = tid & 31;
    int g = lane >> 2, qd = lane & 3;

    __shared__ __align__(16) __nv_bfloat16 sK[64][40];
    __shared__ __align__(16) __nv_bfloat16 sV[64][40];
    uint32 skb = (uint32)__cvta_generic_to_shared(&sK[0][0]);
    uint32 svb = (uint32)__cvta_generic_to_shared(&sV[0][0]);
    int lrow = lane & 7, lgrp = lane >> 3;
    uint32 kaddr = skb + (uint32)(lrow * 80 + lgrp * 16);
    uint32 vaddr = svb + (uint32)((lgrp * 8 + lrow) * 80);

    const __nv_bfloat16* Kb = kbuf + ((size_t)(b * NH + h) * N_) * HD;
    const __nv_bfloat16* Vb = vbuf + ((size_t)(b * NH + h) * N_) * HD;
    const __nv_bfloat16* Qb = qbuf + ((size_t)(b * NH + h) * N_) * HD;

    int base = qt * 128 + warp * 32;

    uint32 qa[2][2][4];
#pragma unroll
    for (int mt = 0; mt < 2; mt++) {
        int r0 = min(base + mt * 16 + g,     N_ - 1);
        int r1 = min(base + mt * 16 + g + 8, N_ - 1);
        const __nv_bfloat16* q0 = Qb + (size_t)r0 * HD;
        const __nv_bfloat16* q1 = Qb + (size_t)r1 * HD;
#pragma unroll
        for (int kk = 0; kk < 2; kk++) {
            int c0 = kk * 16 + 2 * qd;
            qa[mt][kk][0] = *(const uint32*)(q0 + c0);
            qa[mt][kk][1] = *(const uint32*)(q1 + c0);
            qa[mt][kk][2] = *(const uint32*)(q0 + c0 + 8);
            qa[mt][kk][3] = *(const uint32*)(q1 + c0 + 8);
        }
    }

    float oacc[2][4][4];
#pragma unroll
    for (int mt = 0; mt < 2; mt++)
#pragma unroll
        for (int nd = 0; nd < 4; nd++)
#pragma unroll
            for (int j = 0; j < 4; j++) oacc[mt][nd][j] = 0.f;
    float lsum[2][2] = {{0.f, 0.f}, {0.f, 0.f}};

    int key0 = tid >> 2;
    int d8   = (tid & 3) * 8;
    int key1 = (tid + 128) >> 2;
    int d8b  = ((tid + 128) & 3) * 8;

    for (int kb = 0; kb < N_; kb += 64) {
        int mc0 = min(kb + key0, N_ - 1);
        int mc1 = min(kb + key1, N_ - 1);
        *(uint4*)&sK[key0][d8]  = *(const uint4*)(Kb + (size_t)mc0 * HD + d8);
        *(uint4*)&sV[key0][d8]  = *(const uint4*)(Vb + (size_t)mc0 * HD + d8);
        *(uint4*)&sK[key1][d8b] = *(const uint4*)(Kb + (size_t)mc1 * HD + d8b);
        *(uint4*)&sV[key1][d8b] = *(const uint4*)(Vb + (size_t)mc1 * HD + d8b);
        __syncthreads();

        if (kb + 64 <= N_) attn_tile<false>(kb, qd, kaddr, vaddr, qa, oacc, lsum);
        else               attn_tile<true >(kb, qd, kaddr, vaddr, qa, oacc, lsum);
        __syncthreads();
    }

#pragma unroll
    for (int mt = 0; mt < 2; mt++)
#pragma unroll
        for (int half = 0; half < 2; half++) {
            float v = lsum[mt][half];
            v += __shfl_xor_sync(0xffffffffu, v, 1);
            v += __shfl_xor_sync(0xffffffffu, v, 2);
            lsum[mt][half] = 1.f / v;
        }

#pragma unroll
    for (int mt = 0; mt < 2; mt++)
#pragma unroll
        for (int half = 0; half < 2; half++) {
            int row = base + mt * 16 + half * 8 + g;
            if (row >= N_) continue;
            float inv = lsum[mt][half];
            float* op = o_out + (size_t)(b * N_ + row) * C_ + h * HD;
#pragma unroll
            for (int nd = 0; nd < 4; nd++)
                *(float2*)(op + nd * 8 + 2 * qd) =
                    make_float2(oacc[mt][nd][half * 2] * inv,
                                oacc[mt][nd][half * 2 + 1] * inv);
        }
}

// ---------------------------------------------------------------------------
// Host launch
// ---------------------------------------------------------------------------
extern "C" void kernel_launch(void* const* d_in, const int* in_sizes, int n_in,
                              void* d_out, int out_size) {
    const float* x       = (const float*)d_in[0];
    const float* W_pe    = (const float*)d_in[1];
    const float* b_pe    = (const float*)d_in[2];
    const float* cls     = (const float*)d_in[3];
    const float* ln1_g   = (const float*)d_in[4];
    const float* ln1_b   = (const float*)d_in[5];
    const float* Wqkv    = (const float*)d_in[6];
    const float* Wproj   = (const float*)d_in[7];
    const float* bproj   = (const float*)d_in[8];
    const float* ln2_g   = (const float*)d_in[9];
    const float* ln2_b   = (const float*)d_in[10];
    const float* W1      = (const float*)d_in[11];
    const float* b1      = (const float*)d_in[12];
    const float* W2      = (const float*)d_in[13];
    const float* b2      = (const float*)d_in[14];
    const float* normf_g = (const float*)d_in[15];
    const float* normf_b = (const float*)d_in[16];
    float* out = (float*)d_out;

    float *t, *y, *h, *o;
    __nv_bfloat16 *qb, *kb, *vb;
    cudaGetSymbolAddress((void**)&t,  g_t);
    cudaGetSymbolAddress((void**)&y,  g_y);
    cudaGetSymbolAddress((void**)&h,  g_h);
    cudaGetSymbolAddress((void**)&o,  g_o);
    cudaGetSymbolAddress((void**)&qb, g_qb);
    cudaGetSymbolAddress((void**)&kb, g_kb);
    cudaGetSymbolAddress((void**)&vb, g_vb);

    const int M = M_TOK;
    int mtiles = (M + 63) / 64;                 // 109
    dim3 gridQKV(12, mtiles);                   // BN=64, N=768
    dim3 gridC(8, mtiles);                      // BN=32, N=256
    dim3 gridAttn((N_ + 127) / 128, B_ * NH);   // 14 x 32 = 448
    dim3 gridFLN((N_ + 31) / 32, B_);           // 55 x 4
    int lnBlocks = (M + 7) / 8;                 // 865

    embed_kernel<<<dim3(P_ / 8, B_), 256>>>(x, W_pe, b_pe, cls);

    for (int i = 0; i < DEPTH; i++) {
        const float* wqkv  = Wqkv  + i * C_ * 3 * C_;
        const float* wproj = Wproj + i * C_ * C_;
        const float* w1    = W1    + i * C_ * C_;
        const float* w2    = W2    + i * C_ * C_;

        ln_kernel<<<lnBlocks, 256>>>(t, y, ln1_g + i * C_, ln1_b + i * C_);
        gemm_tf32<4, true, false, false><<<gridQKV, 128>>>(
            y, wqkv, nullptr, nullptr, M, C_, 3 * C_, qb, kb, vb);
        attn_kernel<<<gridAttn, 128>>>(qb, kb, vb, o);
        gemm_tf32<2, false, false, true><<<gridC, 128>>>(
            o, wproj, bproj + i * C_, t, M, C_, C_, nullptr, nullptr, nullptr);
        ln_kernel<<<lnBlocks, 256>>>(t, y, ln2_g + i * C_, ln2_b + i * C_);
        gemm_tf32<2, false, true, false><<<gridC, 128>>>(
            y, w1, b1 + i * C_, h, M, C_, C_, nullptr, nullptr, nullptr);
        gemm_tf32<2, false, false, true><<<gridC, 128>>>(
            h, w2, b2 + i * C_, t, M, C_, C_, nullptr, nullptr, nullptr);
    }

    final_ln_kernel<<<gridFLN, 256>>>(t, normf_g, normf_b, out);
}

// round 17
// speedup vs baseline: 1.0738x; 1.0738x over previous
#include <cuda_runtime.h>
#include <cuda_bf16.h>

// Problem constants
#define B_   4
#define CIN  64
#define C_   256
#define N_   1729          // 1 cls + 12*12*12 tokens
#define P_   1728
#define NH   8
#define HD   32
#define DEPTH 2
#define M_TOK (B_ * N_)    // 6916

typedef unsigned int uint32;

// ---- bf16 helpers ----
__device__ __forceinline__ uint32 bf2(float lo, float hi) {
    __nv_bfloat162 t = __floats2bfloat162_rn(lo, hi);   // lo -> low 16 bits
    return *(uint32*)&t;
}

__device__ __forceinline__ float ex2f(float x) {
    float r; asm("ex2.approx.f32 %0, %1;" : "=f"(r) : "f"(x)); return r;
}

// bf16 m16n8k16 mma: D = A @ B^T + D  (A,B bf16, C/D fp32)
__device__ __forceinline__ void mma16816(float* c, const uint32* a, uint32 b0, uint32 b1) {
    asm volatile(
        "mma.sync.aligned.m16n8k16.row.col.f32.bf16.bf16.f32 "
        "{%0,%1,%2,%3}, {%4,%5,%6,%7}, {%8,%9}, {%0,%1,%2,%3};\n"
        : "+f"(c[0]), "+f"(c[1]), "+f"(c[2]), "+f"(c[3])
        : "r"(a[0]), "r"(a[1]), "r"(a[2]), "r"(a[3]), "r"(b0), "r"(b1));
}

// tf32 m16n8k8 mma
__device__ __forceinline__ void mma_tf32(float* c, const uint32* a, uint32 b0, uint32 b1) {
    asm volatile(
        "mma.sync.aligned.m16n8k8.row.col.f32.tf32.tf32.f32 "
        "{%0,%1,%2,%3}, {%4,%5,%6,%7}, {%8,%9}, {%0,%1,%2,%3};\n"
        : "+f"(c[0]), "+f"(c[1]), "+f"(c[2]), "+f"(c[3])
        : "r"(a[0]), "r"(a[1]), "r"(a[2]), "r"(a[3]), "r"(b0), "r"(b1));
}

__device__ __forceinline__ float cvt_tf32f(float f) {
    uint32 r; asm("cvt.rna.tf32.f32 %0, %1;" : "=r"(r) : "f"(f));
    return __uint_as_float(r);
}

__device__ __forceinline__ void ldsm4(uint32& r0, uint32& r1, uint32& r2, uint32& r3,
                                      uint32 addr) {
    asm volatile("ldmatrix.sync.aligned.m8n8.x4.shared.b16 {%0,%1,%2,%3}, [%4];"
                 : "=r"(r0), "=r"(r1), "=r"(r2), "=r"(r3) : "r"(addr));
}
__device__ __forceinline__ void ldsm4t(uint32& r0, uint32& r1, uint32& r2, uint32& r3,
                                       uint32 addr) {
    asm volatile("ldmatrix.sync.aligned.m8n8.x4.trans.shared.b16 {%0,%1,%2,%3}, [%4];"
                 : "=r"(r0), "=r"(r1), "=r"(r2), "=r"(r3) : "r"(addr));
}

// ---- cp.async helpers ----
__device__ __forceinline__ void cpasync16(uint32 dst, const void* src) {
    asm volatile("cp.async.cg.shared.global [%0], [%1], 16;" :: "r"(dst), "l"(src));
}
__device__ __forceinline__ void cp_commit() {
    asm volatile("cp.async.commit_group;");
}
__device__ __forceinline__ void cp_wait0() {
    asm volatile("cp.async.wait_group 0;" ::: "memory");
}

// Scratch (device globals; no cudaMalloc allowed)
__device__ float g_t  [M_TOK * C_];
__device__ float g_y  [M_TOK * C_];
__device__ float g_h  [M_TOK * C_];
__device__ float g_o  [M_TOK * C_];
// bf16 Q/K/V head-major [b, h, n, 32]; Q pre-scaled by log2(e)/sqrt(hd)
__device__ __nv_bfloat16 g_qb[B_ * NH * N_ * HD];
__device__ __nv_bfloat16 g_kb[B_ * NH * N_ * HD];
__device__ __nv_bfloat16 g_vb[B_ * NH * N_ * HD];

// ---------------------------------------------------------------------------
// Patch embed: 8 tokens per block, W_pe values reused x8.
// ---------------------------------------------------------------------------
__global__ __launch_bounds__(256) void embed_kernel(const float* __restrict__ x,
                                                    const float* __restrict__ W_pe,
                                                    const float* __restrict__ b_pe,
                                                    const float* __restrict__ cls) {
    int p0 = blockIdx.x * 8;
    int b  = blockIdx.y;
    int d  = threadIdx.x;

    __shared__ float sx[CIN][8];
#pragma unroll
    for (int i = 0; i < 2; i++) {
        int idx = d + i * 256;
        int c = idx >> 3, tok = idx & 7;
        sx[c][tok] = x[(size_t)(b * CIN + c) * P_ + p0 + tok];
    }
    __syncthreads();

    float acc[8];
    float bp = b_pe[d];
#pragma unroll
    for (int t = 0; t < 8; t++) acc[t] = bp;
#pragma unroll
    for (int c = 0; c < CIN; c++) {
        float w = W_pe[c * C_ + d];
        float4 x0 = *(const float4*)&sx[c][0];
        float4 x1 = *(const float4*)&sx[c][4];
        acc[0] += x0.x * w; acc[1] += x0.y * w;
        acc[2] += x0.z * w; acc[3] += x0.w * w;
        acc[4] += x1.x * w; acc[5] += x1.y * w;
        acc[6] += x1.z * w; acc[7] += x1.w * w;
    }
#pragma unroll
    for (int t = 0; t < 8; t++)
        g_t[(size_t)(b * N_ + 1 + p0 + t) * C_ + d] = acc[t];

    if (blockIdx.x == 0) g_t[(size_t)(b * N_) * C_ + d] = cls[d];
}

// ---------------------------------------------------------------------------
// LayerNorm: warp-per-row, float4 loads, shuffle-only reduction. 8 rows/block.
// ---------------------------------------------------------------------------
__global__ __launch_bounds__(256) void ln_kernel(const float* __restrict__ in,
                                                 float* __restrict__ out,
                                                 const float* __restrict__ g,
                                                 const float* __restrict__ bb) {
    int row = blockIdx.x * 8 + (threadIdx.x >> 5);
    int lane = threadIdx.x & 31;
    if (row >= M_TOK) return;
    const float4* rp = (const float4*)(in + (size_t)row * C_);
    float4 v0 = rp[lane], v1 = rp[lane + 32];
    float s  = (v0.x + v0.y) + (v0.z + v0.w) + (v1.x + v1.y) + (v1.z + v1.w);
    float sq = (v0.x * v0.x + v0.y * v0.y) + (v0.z * v0.z + v0.w * v0.w)
             + (v1.x * v1.x + v1.y * v1.y) + (v1.z * v1.z + v1.w * v1.w);
#pragma unroll
    for (int o = 16; o > 0; o >>= 1) {
        s  += __shfl_xor_sync(0xffffffffu, s,  o);
        sq += __shfl_xor_sync(0xffffffffu, sq, o);
    }
    float mean = s * (1.f / C_);
    float var  = sq * (1.f / C_) - mean * mean;
    float inv  = rsqrtf(var + 1e-5f);

    const float4* gp = (const float4*)g;
    const float4* bp = (const float4*)bb;
    float4* op = (float4*)(out + (size_t)row * C_);
#pragma unroll
    for (int k = 0; k < 2; k++) {
        float4 v = k ? v1 : v0;
        float4 gg = gp[lane + k * 32];
        float4 bbv = bp[lane + k * 32];
        float4 r;
        r.x = (v.x - mean) * inv * gg.x + bbv.x;
        r.y = (v.y - mean) * inv * gg.y + bbv.y;
        r.z = (v.z - mean) * inv * gg.z + bbv.z;
        r.w = (v.w - mean) * inv * gg.w + bbv.w;
        op[lane + k * 32] = r;
    }
}

// ---------------------------------------------------------------------------
// Final LN + transposed scatter, coalesced: 32-token chunk per block.
// ---------------------------------------------------------------------------
__global__ __launch_bounds__(256) void final_ln_kernel(const float* __restrict__ in,
                                                       const float* __restrict__ g,
                                                       const float* __restrict__ bb,
                                                       float* __restrict__ out) {
    __shared__ float tile[32 * 257];
    int b  = blockIdx.y;
    int n0 = blockIdx.x * 32;
    int tid = threadIdx.x;
    int warp = tid >> 5, lane = tid & 31;

#pragma unroll
    for (int i = 0; i < 4; i++) {
        int j = warp + i * 8;            // local row 0..31
        int n = n0 + j;
        if (n >= N_) break;
        const float* rp = in + (size_t)(b * N_ + n) * C_;
        float v[8];
        float s = 0.f, sq = 0.f;
#pragma unroll
        for (int k = 0; k < 8; k++) {
            v[k] = rp[lane + k * 32];
            s += v[k]; sq += v[k] * v[k];
        }
#pragma unroll
        for (int o = 16; o > 0; o >>= 1) {
            s  += __shfl_xor_sync(0xffffffffu, s,  o);
            sq += __shfl_xor_sync(0xffffffffu, sq, o);
        }
        float mean = s * (1.f / C_);
        float var  = sq * (1.f / C_) - mean * mean;
        float inv  = rsqrtf(var + 1e-5f);
#pragma unroll
        for (int k = 0; k < 8; k++) {
            int c = lane + k * 32;
            tile[j * 257 + c] = (v[k] - mean) * inv * g[c] + bb[c];
        }
    }
    __syncthreads();

    int n = n0 + lane;
    if (n >= N_) return;
#pragma unroll
    for (int i = 0; i < 32; i++) {
        int c = warp + i * 8;
        float val = tile[lane * 257 + c];
        if (n == 0) out[b * C_ + c] = val;
        else        out[B_ * C_ + (size_t)(b * C_ + c) * P_ + (n - 1)] = val;
    }
}

// ---------------------------------------------------------------------------
// tf32 tensor-core GEMM, BK=32, register prefetch (R15 version — scalar LDS
// fragment loads; the ldmatrix/transposed-B variant regressed in R16).
// BM=64, BN=16*NT. 128 threads = 4 warps (2m x 2n).
// EPI_QKV: writes outputs as bf16 into head-major q/k/v buffers
// (q pre-scaled by log2e/sqrt(hd)).
// ---------------------------------------------------------------------------
template<int NT, bool EPI_QKV, bool GELU, bool RES>
__global__ __launch_bounds__(128) void gemm_tf32(const float* __restrict__ A,
                                                 const float* __restrict__ W,
                                                 const float* __restrict__ bias,
                                                 float* __restrict__ out,
                                                 int M, int K, int N,
                                                 __nv_bfloat16* __restrict__ qb,
                                                 __nv_bfloat16* __restrict__ kb,
                                                 __nv_bfloat16* __restrict__ vb) {
    constexpr int BN  = 16 * NT;
    constexpr int NB4 = BN / 16;            // B float4 loads per thread (BK=32)
    __shared__ float sA[64][36];            // [m][k], stride 36: conflict-free frags
    __shared__ float sB[32][BN + 4];        // [k][n]
    int tid  = threadIdx.x;
    int warp = tid >> 5, lane = tid & 31;
    int g = lane >> 2, qd = lane & 3;
    int wm = warp >> 1, wn = warp & 1;
    int m0 = blockIdx.y * 64;
    int n0 = blockIdx.x * BN;

    float c[2][NT][4];
#pragma unroll
    for (int mt = 0; mt < 2; mt++)
#pragma unroll
        for (int nt = 0; nt < NT; nt++)
#pragma unroll
            for (int j = 0; j < 4; j++) c[mt][nt][j] = 0.f;

    // initial fill (k0 = 0): A 64x32 = 512 float4, 4/thread; B 32xBN
#pragma unroll
    for (int i = 0; i < 4; i++) {
        int idx = tid + i * 128;
        int m = idx >> 3, q = idx & 7;
        int gm = m0 + m;
        float4 av = (gm < M) ? *(const float4*)(A + (size_t)gm * K + q * 4)
                             : make_float4(0.f, 0.f, 0.f, 0.f);
        av.x = cvt_tf32f(av.x); av.y = cvt_tf32f(av.y);
        av.z = cvt_tf32f(av.z); av.w = cvt_tf32f(av.w);
        *(float4*)&sA[m][q * 4] = av;
    }
#pragma unroll
    for (int i = 0; i < NB4; i++) {
        int idx = tid + i * 128;
        int kl = idx / (BN / 4), nl = (idx % (BN / 4)) * 4;
        float4 bv4 = *(const float4*)(W + (size_t)kl * N + n0 + nl);
        bv4.x = cvt_tf32f(bv4.x); bv4.y = cvt_tf32f(bv4.y);
        bv4.z = cvt_tf32f(bv4.z); bv4.w = cvt_tf32f(bv4.w);
        *(float4*)&sB[kl][nl] = bv4;
    }
    __syncthreads();

    for (int k0 = 0; k0 < K; k0 += 32) {
        bool nxt = (k0 + 32) < K;
        float4 apre[4], bpre[NB4];
        if (nxt) {
#pragma unroll
            for (int i = 0; i < 4; i++) {
                int idx = tid + i * 128;
                int m = idx >> 3, q = idx & 7;
                int gm = m0 + m;
                apre[i] = (gm < M) ? *(const float4*)(A + (size_t)gm * K + k0 + 32 + q * 4)
                                   : make_float4(0.f, 0.f, 0.f, 0.f);
            }
#pragma unroll
            for (int i = 0; i < NB4; i++) {
                int idx = tid + i * 128;
                int kl = idx / (BN / 4), nl = (idx % (BN / 4)) * 4;
                bpre[i] = *(const float4*)(W + (size_t)(k0 + 32 + kl) * N + n0 + nl);
            }
        }

#pragma unroll
        for (int ks = 0; ks < 4; ks++) {
            int k8 = ks * 8;
            uint32 a[2][4];
#pragma unroll
            for (int mt = 0; mt < 2; mt++) {
                int mrow = wm * 32 + mt * 16 + g;
                a[mt][0] = __float_as_uint(sA[mrow    ][qd + k8]);
                a[mt][1] = __float_as_uint(sA[mrow + 8][qd + k8]);
                a[mt][2] = __float_as_uint(sA[mrow    ][qd + 4 + k8]);
                a[mt][3] = __float_as_uint(sA[mrow + 8][qd + 4 + k8]);
            }
#pragma unroll
            for (int nt = 0; nt < NT; nt++) {
                int ncol = wn * (8 * NT) + nt * 8 + g;
                uint32 b0 = __float_as_uint(sB[qd + k8    ][ncol]);
                uint32 b1 = __float_as_uint(sB[qd + 4 + k8][ncol]);
#pragma unroll
                for (int mt = 0; mt < 2; mt++)
                    mma_tf32(c[mt][nt], a[mt], b0, b1);
            }
        }
        __syncthreads();

        if (nxt) {
#pragma unroll
            for (int i = 0; i < 4; i++) {
                int idx = tid + i * 128;
                float4 av = apre[i];
                av.x = cvt_tf32f(av.x); av.y = cvt_tf32f(av.y);
                av.z = cvt_tf32f(av.z); av.w = cvt_tf32f(av.w);
                *(float4*)&sA[idx >> 3][(idx & 7) * 4] = av;
            }
#pragma unroll
            for (int i = 0; i < NB4; i++) {
                int idx = tid + i * 128;
                int kl = idx / (BN / 4), nl = (idx % (BN / 4)) * 4;
                float4 bv4 = bpre[i];
                bv4.x = cvt_tf32f(bv4.x); bv4.y = cvt_tf32f(bv4.y);
                bv4.z = cvt_tf32f(bv4.z); bv4.w = cvt_tf32f(bv4.w);
                *(float4*)&sB[kl][nl] = bv4;
            }
            __syncthreads();
        }
    }

    // q scale includes log2(e) so softmax uses raw ex2
    const float qscale = 0.17677669529663687f * 1.4426950408889634f;

#pragma unroll
    for (int nt = 0; nt < NT; nt++) {
        int col = n0 + wn * (8 * NT) + nt * 8 + 2 * qd;
        float bv0 = (!EPI_QKV && bias) ? bias[col]     : 0.f;
        float bv1 = (!EPI_QKV && bias) ? bias[col + 1] : 0.f;
#pragma unroll
        for (int mt = 0; mt < 2; mt++) {
            int row0 = m0 + wm * 32 + mt * 16 + g;
#pragma unroll
            for (int half = 0; half < 2; half++) {
                int row = row0 + half * 8;
                if (row >= M) continue;
                float v0 = c[mt][nt][half * 2];
                float v1 = c[mt][nt][half * 2 + 1];
                if (EPI_QKV) {
                    int seg = col >> 8;
                    int h   = (col & 255) >> 5;
                    int d   = col & 31;
                    int b   = row / N_, n = row % N_;
                    float sc = (seg == 0) ? qscale : 1.f;
                    __nv_bfloat16* dst = (seg == 0) ? qb : (seg == 1) ? kb : vb;
                    *(uint32*)&dst[((size_t)(b * NH + h) * N_ + n) * HD + d] =
                        bf2(v0 * sc, v1 * sc);
                } else {
                    v0 += bv0; v1 += bv1;
                    if (GELU) { v0 = v0 * normcdff(v0); v1 = v1 * normcdff(v1); }
                    float* op = out + (size_t)row * N + col;
                    if (RES) {
                        float2 prev = *(const float2*)op;
                        *(float2*)op = make_float2(prev.x + v0, prev.y + v1);
                    } else {
                        *(float2*)op = make_float2(v0, v1);
                    }
                }
            }
        }
    }
}

// ---------------------------------------------------------------------------
// Attention tile compute: GUARD=false for fully-valid tiles (no predicates).
// ---------------------------------------------------------------------------
template<bool GUARD>
__device__ __forceinline__ void attn_tile(int kb, int qd, uint32 kaddr, uint32 vaddr,
                                          const uint32 qa[2][2][4],
                                          float oacc[2][4][4], float lsum[2][2]) {
    uint32 pa[2][4][4];
#pragma unroll
    for (int ns = 0; ns < 8; ns++) {
        uint32 b0, b1, b2, b3;
        ldsm4(b0, b1, b2, b3, kaddr + ns * 640);
        float s0[4] = {0.f, 0.f, 0.f, 0.f};
        float s1[4] = {0.f, 0.f, 0.f, 0.f};
        mma16816(s0, qa[0][0], b0, b1);
        mma16816(s0, qa[0][1], b2, b3);
        mma16816(s1, qa[1][0], b0, b1);
        mma16816(s1, qa[1][1], b2, b3);

        float p00, p01, p02, p03, p10, p11, p12, p13;
        if (GUARD) {
            int cb = kb + ns * 8 + 2 * qd;
            bool v0 = cb < N_, v1 = (cb + 1) < N_;
            p00 = v0 ? ex2f(s0[0]) : 0.f;
            p01 = v1 ? ex2f(s0[1]) : 0.f;
            p02 = v0 ? ex2f(s0[2]) : 0.f;
            p03 = v1 ? ex2f(s0[3]) : 0.f;
            p10 = v0 ? ex2f(s1[0]) : 0.f;
            p11 = v1 ? ex2f(s1[1]) : 0.f;
            p12 = v0 ? ex2f(s1[2]) : 0.f;
            p13 = v1 ? ex2f(s1[3]) : 0.f;
        } else {
            p00 = ex2f(s0[0]); p01 = ex2f(s0[1]);
            p02 = ex2f(s0[2]); p03 = ex2f(s0[3]);
            p10 = ex2f(s1[0]); p11 = ex2f(s1[1]);
            p12 = ex2f(s1[2]); p13 = ex2f(s1[3]);
        }
        lsum[0][0] += p00 + p01; lsum[0][1] += p02 + p03;
        lsum[1][0] += p10 + p11; lsum[1][1] += p12 + p13;

        int kk = ns >> 1;
        if (ns & 1) {
            pa[0][kk][2] = bf2(p00, p01); pa[0][kk][3] = bf2(p02, p03);
            pa[1][kk][2] = bf2(p10, p11); pa[1][kk][3] = bf2(p12, p13);
        } else {
            pa[0][kk][0] = bf2(p00, p01); pa[0][kk][1] = bf2(p02, p03);
            pa[1][kk][0] = bf2(p10, p11); pa[1][kk][1] = bf2(p12, p13);
        }
    }

#pragma unroll
    for (int nd = 0; nd < 4; nd++) {
        uint32 b0, b1, b2, b3;
        ldsm4t(b0, b1, b2, b3, vaddr + nd * 16);
        mma16816(oacc[0][nd], pa[0][0], b0, b1);
        mma16816(oacc[0][nd], pa[0][1], b2, b3);
        mma16816(oacc[1][nd], pa[1][0], b0, b1);
        mma16816(oacc[1][nd], pa[1][1], b2, b3);
        ldsm4t(b0, b1, b2, b3, vaddr + nd * 16 + 2560);
        mma16816(oacc[0][nd], pa[0][2], b0, b1);
        mma16816(oacc[0][nd], pa[0][3], b2, b3);
        mma16816(oacc[1][nd], pa[1][2], b0, b1);
        mma16816(oacc[1][nd], pa[1][3], b2, b3);
    }
}

// ---------------------------------------------------------------------------
// bf16 tensor-core flash attention, cp.async double-buffered K/V tiles.
// One __syncthreads per tile; next tile's loads (LDGSTS, no GPR staging)
// complete during the current tile's 24 mmas + 32 ex2.
// 128 q/CTA, 32 q/warp. Grid 14 x 32 = 448 CTAs.
// ---------------------------------------------------------------------------
__global__ __launch_bounds__(128) void attn_kernel(const __nv_bfloat16* __restrict__ qbuf,
                                                   const __nv_bfloat16* __restrict__ kbuf,
                                                   const __nv_bfloat16* __restrict__ vbuf,
                                                   float* __restrict__ o_out) {
    int qt  = blockIdx.x;
    int bh  = blockIdx.y;
    int b   = bh >> 3;
    int h   = bh & 7;
    int tid = threadIdx.x;
    int warp = tid >> 5, lane = tid & 31;
    int g = lane >> 2, qd = lane & 3;

    __shared__ __align__(16) __nv_bfloat16 sK[2][64][40];
    __shared__ __align__(16) __nv_bfloat16 sV[2][64][40];
    constexpr uint32 BUFB = 64 * 40 * 2;   // bytes per buffer (5120)
    uint32 skb = (uint32)__cvta_generic_to_shared(&sK[0][0][0]);
    uint32 svb = (uint32)__cvta_generic_to_shared(&sV[0][0][0]);
    int lrow = lane & 7, lgrp = lane >> 3;
    uint32 kaddr0 = skb + (uint32)(lrow * 80 + lgrp * 16);
    uint32 vaddr0 = svb + (uint32)((lgrp * 8 + lrow) * 80);

    const __nv_bfloat16* Kb = kbuf + ((size_t)(b * NH + h) * N_) * HD;
    const __nv_bfloat16* Vb = vbuf + ((size_t)(b * NH + h) * N_) * HD;
    const __nv_bfloat16* Qb = qbuf + ((size_t)(b * NH + h) * N_) * HD;

    int base = qt * 128 + warp * 32;

    uint32 qa[2][2][4];
#pragma unroll
    for (int mt = 0; mt < 2; mt++) {
        int r0 = min(base + mt * 16 + g,     N_ - 1);
        int r1 = min(base + mt * 16 + g + 8, N_ - 1);
        const __nv_bfloat16* q0 = Qb + (size_t)r0 * HD;
        const __nv_bfloat16* q1 = Qb + (size_t)r1 * HD;
#pragma unroll
        for (int kk = 0; kk < 2; kk++) {
            int c0 = kk * 16 + 2 * qd;
            qa[mt][kk][0] = *(const uint32*)(q0 + c0);
            qa[mt][kk][1] = *(const uint32*)(q1 + c0);
            qa[mt][kk][2] = *(const uint32*)(q0 + c0 + 8);
            qa[mt][kk][3] = *(const uint32*)(q1 + c0 + 8);
        }
    }

    float oacc[2][4][4];
#pragma unroll
    for (int mt = 0; mt < 2; mt++)
#pragma unroll
        for (int nd = 0; nd < 4; nd++)
#pragma unroll
            for (int j = 0; j < 4; j++) oacc[mt][nd][j] = 0.f;
    float lsum[2][2] = {{0.f, 0.f}, {0.f, 0.f}};

    // per-thread tile-load slots (fixed across tiles)
    int key0 = tid >> 2;
    int d8   = (tid & 3) * 8;
    int key1 = (tid + 128) >> 2;
    int d8b  = ((tid + 128) & 3) * 8;
    uint32 kd0 = skb + (uint32)(key0 * 80 + d8  * 2);
    uint32 vd0 = svb + (uint32)(key0 * 80 + d8  * 2);
    uint32 kd1 = skb + (uint32)(key1 * 80 + d8b * 2);
    uint32 vd1 = svb + (uint32)(key1 * 80 + d8b * 2);

    // prologue: issue tile 0 into buffer 0
    {
        int mc0 = min(key0, N_ - 1);
        int mc1 = min(key1, N_ - 1);
        cpasync16(kd0, Kb + (size_t)mc0 * HD + d8);
        cpasync16(vd0, Vb + (size_t)mc0 * HD + d8);
        cpasync16(kd1, Kb + (size_t)mc1 * HD + d8b);
        cpasync16(vd1, Vb + (size_t)mc1 * HD + d8b);
        cp_commit();
    }

    int buf = 0;
    for (int kb = 0; kb < N_; kb += 64) {
        cp_wait0();
        __syncthreads();

        bool nxt = (kb + 64) < N_;
        if (nxt) {
            int nb = buf ^ 1;
            int mc0 = min(kb + 64 + key0, N_ - 1);
            int mc1 = min(kb + 64 + key1, N_ - 1);
            cpasync16(kd0 + nb * BUFB, Kb + (size_t)mc0 * HD + d8);
            cpasync16(vd0 + nb * BUFB, Vb + (size_t)mc0 * HD + d8);
            cpasync16(kd1 + nb * BUFB, Kb + (size_t)mc1 * HD + d8b);
            cpasync16(vd1 + nb * BUFB, Vb + (size_t)mc1 * HD + d8b);
            cp_commit();
        }

        uint32 kaddr = kaddr0 + buf * BUFB;
        uint32 vaddr = vaddr0 + buf * BUFB;
        if (kb + 64 <= N_) attn_tile<false>(kb, qd, kaddr, vaddr, qa, oacc, lsum);
        else               attn_tile<true >(kb, qd, kaddr, vaddr, qa, oacc, lsum);
        buf ^= 1;
    }

#pragma unroll
    for (int mt = 0; mt < 2; mt++)
#pragma unroll
        for (int half = 0; half < 2; half++) {
            float v = lsum[mt][half];
            v += __shfl_xor_sync(0xffffffffu, v, 1);
            v += __shfl_xor_sync(0xffffffffu, v, 2);
            lsum[mt][half] = 1.f / v;
        }

#pragma unroll
    for (int mt = 0; mt < 2; mt++)
#pragma unroll
        for (int half = 0; half < 2; half++) {
            int row = base + mt * 16 + half * 8 + g;
            if (row >= N_) continue;
            float inv = lsum[mt][half];
            float* op = o_out + (size_t)(b * N_ + row) * C_ + h * HD;
#pragma unroll
            for (int nd = 0; nd < 4; nd++)
                *(float2*)(op + nd * 8 + 2 * qd) =
                    make_float2(oacc[mt][nd][half * 2] * inv,
                                oacc[mt][nd][half * 2 + 1] * inv);
        }
}

// ---------------------------------------------------------------------------
// Host launch
// ---------------------------------------------------------------------------
extern "C" void kernel_launch(void* const* d_in, const int* in_sizes, int n_in,
                              void* d_out, int out_size) {
    const float* x       = (const float*)d_in[0];
    const float* W_pe    = (const float*)d_in[1];
    const float* b_pe    = (const float*)d_in[2];
    const float* cls     = (const float*)d_in[3];
    const float* ln1_g   = (const float*)d_in[4];
    const float* ln1_b   = (const float*)d_in[5];
    const float* Wqkv    = (const float*)d_in[6];
    const float* Wproj   = (const float*)d_in[7];
    const float* bproj   = (const float*)d_in[8];
    const float* ln2_g   = (const float*)d_in[9];
    const float* ln2_b   = (const float*)d_in[10];
    const float* W1      = (const float*)d_in[11];
    const float* b1      = (const float*)d_in[12];
    const float* W2      = (const float*)d_in[13];
    const float* b2      = (const float*)d_in[14];
    const float* normf_g = (const float*)d_in[15];
    const float* normf_b = (const float*)d_in[16];
    float* out = (float*)d_out;

    float *t, *y, *h, *o;
    __nv_bfloat16 *qb, *kb, *vb;
    cudaGetSymbolAddress((void**)&t,  g_t);
    cudaGetSymbolAddress((void**)&y,  g_y);
    cudaGetSymbolAddress((void**)&h,  g_h);
    cudaGetSymbolAddress((void**)&o,  g_o);
    cudaGetSymbolAddress((void**)&qb, g_qb);
    cudaGetSymbolAddress((void**)&kb, g_kb);
    cudaGetSymbolAddress((void**)&vb, g_vb);

    const int M = M_TOK;
    int mtiles = (M + 63) / 64;                 // 109
    dim3 gridQKV(12, mtiles);                   // BN=64, N=768
    dim3 gridC(8, mtiles);                      // BN=32, N=256
    dim3 gridAttn((N_ + 127) / 128, B_ * NH);   // 14 x 32 = 448
    dim3 gridFLN((N_ + 31) / 32, B_);           // 55 x 4
    int lnBlocks = (M + 7) / 8;                 // 865

    embed_kernel<<<dim3(P_ / 8, B_), 256>>>(x, W_pe, b_pe, cls);

    for (int i = 0; i < DEPTH; i++) {
        const float* wqkv  = Wqkv  + i * C_ * 3 * C_;
        const float* wproj = Wproj + i * C_ * C_;
        const float* w1    = W1    + i * C_ * C_;
        const float* w2    = W2    + i * C_ * C_;

        ln_kernel<<<lnBlocks, 256>>>(t, y, ln1_g + i * C_, ln1_b + i * C_);
        gemm_tf32<4, true, false, false><<<gridQKV, 128>>>(
            y, wqkv, nullptr, nullptr, M, C_, 3 * C_, qb, kb, vb);
        attn_kernel<<<gridAttn, 128>>>(qb, kb, vb, o);
        gemm_tf32<2, false, false, true><<<gridC, 128>>>(
            o, wproj, bproj + i * C_, t, M, C_, C_, nullptr, nullptr, nullptr);
        ln_kernel<<<lnBlocks, 256>>>(t, y, ln2_g + i * C_, ln2_b + i * C_);
        gemm_tf32<2, false, true, false><<<gridC, 128>>>(
            y, w1, b1 + i * C_, h, M, C_, C_, nullptr, nullptr, nullptr);
        gemm_tf32<2, false, false, true><<<gridC, 128>>>(
            h, w2, b2 + i * C_, t, M, C_, C_, nullptr, nullptr, nullptr);
    }

    final_ln_kernel<<<gridFLN, 256>>>(t, normf_g, normf_b, out);
}